// round 5
// baseline (speedup 1.0000x reference)
#include <cuda_runtime.h>
#include <math_constants.h>

// Problem constants (fixed by the reference: centers [8, 4096, 3] fp32)
#define BATCH      8
#define NPTS       4096
#define I_TILE     128
#define NTHREADS   128
#define TILES_PER_B (NPTS / I_TILE)        // 32
#define NBLOCKS    (BATCH * TILES_PER_B)   // 256
#define TARGET_F   0.2f

// Per-block partial sums (device global: no allocation allowed)
__device__ float g_partials[NBLOCKS];

__global__ void __launch_bounds__(NTHREADS)
nn_min_kernel(const float* __restrict__ centers)
{
    // Whole batch cached as float4 (x, y, z, |p|^2): 4096 * 16 B = 64 KB
    extern __shared__ float4 sp[];

    const int blk  = blockIdx.x;
    const int b    = blk / TILES_PER_B;
    const int tile = blk % TILES_PER_B;
    const int tid  = threadIdx.x;

    const float* cb = centers + (size_t)b * NPTS * 3;

    // Fill shared: compute sq on the fly
    for (int p = tid; p < NPTS; p += NTHREADS) {
        float x = cb[3 * p + 0];
        float y = cb[3 * p + 1];
        float z = cb[3 * p + 2];
        sp[p] = make_float4(x, y, z, fmaf(x, x, fmaf(y, y, z * z)));
    }
    __syncthreads();

    // This thread's point i (global index within the batch)
    const int i = tile * I_TILE + tid;
    const float4 me = sp[i];
    const float ax = -2.0f * me.x;
    const float ay = -2.0f * me.y;
    const float az = -2.0f * me.z;

    // min over t_j = sq_j - 2 * <p_i, p_j>   (sq_i added once at the end)
    float tmin = CUDART_INF_F;

    // Diagonal excluded structurally: j in [0, i) then (i, NPTS).
    // Lanes have consecutive i -> warp divergence overhead ~32/4096.
    #pragma unroll 4
    for (int j = 0; j < i; ++j) {
        float4 p = sp[j];
        float t = fmaf(p.x, ax, fmaf(p.y, ay, fmaf(p.z, az, p.w)));
        tmin = fminf(tmin, t);
    }
    #pragma unroll 4
    for (int j = i + 1; j < NPTS; ++j) {
        float4 p = sp[j];
        float t = fmaf(p.x, ax, fmaf(p.y, ay, fmaf(p.z, az, p.w)));
        tmin = fminf(tmin, t);
    }

    float d2   = fmaxf(me.w + tmin, 0.0f);   // clamp like reference
    float md   = sqrtf(d2);
    float diff = md - TARGET_F;
    float v    = diff * diff;

    // Deterministic block reduction
    __shared__ float red[NTHREADS];
    red[tid] = v;
    __syncthreads();
    #pragma unroll
    for (int s = NTHREADS / 2; s > 0; s >>= 1) {
        if (tid < s) red[tid] += red[tid + s];
        __syncthreads();
    }
    if (tid == 0) g_partials[blk] = red[0];
}

__global__ void __launch_bounds__(NBLOCKS)
nn_reduce_kernel(float* __restrict__ out)
{
    __shared__ float red[NBLOCKS];
    const int tid = threadIdx.x;
    red[tid] = g_partials[tid];
    __syncthreads();
    #pragma unroll
    for (int s = NBLOCKS / 2; s > 0; s >>= 1) {
        if (tid < s) red[tid] += red[tid + s];
        __syncthreads();
    }
    if (tid == 0) out[0] = red[0] * (1.0f / (float)(BATCH * NPTS));
}

extern "C" void kernel_launch(void* const* d_in, const int* in_sizes, int n_in,
                              void* d_out, int out_size)
{
    const float* centers = (const float*)d_in[0];
    float* out = (float*)d_out;

    // 64 KB dynamic smem requires opt-in (idempotent; not a stream op, capture-safe)
    cudaFuncSetAttribute(nn_min_kernel,
                         cudaFuncAttributeMaxDynamicSharedMemorySize,
                         NPTS * (int)sizeof(float4));

    nn_min_kernel<<<NBLOCKS, NTHREADS, NPTS * sizeof(float4)>>>(centers);
    nn_reduce_kernel<<<1, NBLOCKS>>>(out);
}

// round 6
// speedup vs baseline: 1.7286x; 1.7286x over previous
#include <cuda_runtime.h>
#include <math_constants.h>

// Problem constants (fixed: centers [8, 4096, 3] fp32)
#define BATCH    8
#define NPTS     4096
#define TPB      128         // threads per block (min kernel)
#define IPT      4           // i-points per thread
#define ITILE    (TPB * IPT) // 512 i per block
#define NITILES  (NPTS / ITILE)   // 8
#define SSPLIT   8           // j-splits
#define JT       (NPTS / SSPLIT)  // 512 j per block  (== ITILE, aligned)
#define NBLK_MIN (BATCH * NITILES * SSPLIT)  // 512
#define CMB_TPB  512
#define NBLK_CMB ((BATCH * NPTS) / CMB_TPB)  // 64
#define TARGET_F 0.2f

// Scratch (static device globals — no allocation allowed)
// g_pmin4: per-point partial mins, layout [i][SSPLIT] floats = [i][2] float4
__device__ float4 g_pmin4[BATCH * NPTS * SSPLIT / 4];
__device__ float  g_partials[NBLK_CMB];

__global__ void __launch_bounds__(TPB)
nn_min_kernel(const float* __restrict__ centers)
{
    __shared__ float4 spj[JT];   // 8 KB: j-tile as (x, y, z, |p|^2)

    const int blk = blockIdx.x;
    const int s   = blk & (SSPLIT - 1);            // j-split index
    const int it  = (blk / SSPLIT) & (NITILES - 1);// i-tile index
    const int b   = blk / (SSPLIT * NITILES);      // batch
    const int tid = threadIdx.x;

    const float* cb = centers + (size_t)b * NPTS * 3;
    const int j_lo  = s  * JT;
    const int i_lo  = it * ITILE;

    // Stage j-tile into shared, computing |p|^2 on the fly
    for (int p = tid; p < JT; p += TPB) {
        float x = cb[3 * (j_lo + p) + 0];
        float y = cb[3 * (j_lo + p) + 1];
        float z = cb[3 * (j_lo + p) + 2];
        spj[p] = make_float4(x, y, z, fmaf(x, x, fmaf(y, y, z * z)));
    }

    // This thread's IPT i-points
    float ax[IPT], ay[IPT], az[IPT], sqi[IPT], tmin[IPT];
    int   iloc[IPT];
    #pragma unroll
    for (int k = 0; k < IPT; ++k) {
        iloc[k] = tid + k * TPB;
        const int gi = i_lo + iloc[k];
        float x = cb[3 * gi + 0];
        float y = cb[3 * gi + 1];
        float z = cb[3 * gi + 2];
        ax[k] = -2.0f * x;  ay[k] = -2.0f * y;  az[k] = -2.0f * z;
        sqi[k] = fmaf(x, x, fmaf(y, y, z * z));
        tmin[k] = CUDART_INF_F;
    }
    __syncthreads();

    // min over t_j = sq_j - 2*<p_i, p_j>    (sq_i added once at the end)
    if (it != s) {
        // Off-diagonal block: clean constant-trip loop, no compares
        #pragma unroll 8
        for (int j = 0; j < JT; ++j) {
            const float4 p = spj[j];
            #pragma unroll
            for (int k = 0; k < IPT; ++k) {
                float t = fmaf(p.x, ax[k], fmaf(p.y, ay[k], fmaf(p.z, az[k], p.w)));
                tmin[k] = fminf(tmin[k], t);
            }
        }
    } else {
        // Diagonal block (1/SSPLIT of blocks): predicate out j == i
        #pragma unroll 4
        for (int j = 0; j < JT; ++j) {
            const float4 p = spj[j];
            #pragma unroll
            for (int k = 0; k < IPT; ++k) {
                float t = fmaf(p.x, ax[k], fmaf(p.y, ay[k], fmaf(p.z, az[k], p.w)));
                t = (j == iloc[k]) ? CUDART_INF_F : t;
                tmin[k] = fminf(tmin[k], t);
            }
        }
    }

    // Emit partial (sq_i + tmin) for each i
    float* pm = (float*)g_pmin4;
    #pragma unroll
    for (int k = 0; k < IPT; ++k) {
        const int gi = (b * NPTS) + i_lo + iloc[k];
        pm[(size_t)gi * SSPLIT + s] = sqi[k] + tmin[k];
    }
}

__global__ void __launch_bounds__(CMB_TPB)
nn_combine_kernel()
{
    __shared__ float red[CMB_TPB];
    const int tid = threadIdx.x;
    const int gi  = blockIdx.x * CMB_TPB + tid;

    const float4 a = g_pmin4[gi * 2 + 0];
    const float4 c = g_pmin4[gi * 2 + 1];
    float m = fminf(fminf(fminf(a.x, a.y), fminf(a.z, a.w)),
                    fminf(fminf(c.x, c.y), fminf(c.z, c.w)));
    float d2   = fmaxf(m, 0.0f);     // clamp like reference
    float diff = sqrtf(d2) - TARGET_F;
    red[tid] = diff * diff;
    __syncthreads();
    #pragma unroll
    for (int st = CMB_TPB / 2; st > 0; st >>= 1) {
        if (tid < st) red[tid] += red[tid + st];
        __syncthreads();
    }
    if (tid == 0) g_partials[blockIdx.x] = red[0];
}

__global__ void __launch_bounds__(NBLK_CMB)
nn_final_kernel(float* __restrict__ out)
{
    __shared__ float red[NBLK_CMB];
    const int tid = threadIdx.x;
    red[tid] = g_partials[tid];
    __syncthreads();
    #pragma unroll
    for (int st = NBLK_CMB / 2; st > 0; st >>= 1) {
        if (tid < st) red[tid] += red[tid + st];
        __syncthreads();
    }
    if (tid == 0) out[0] = red[0] * (1.0f / (float)(BATCH * NPTS));
}

extern "C" void kernel_launch(void* const* d_in, const int* in_sizes, int n_in,
                              void* d_out, int out_size)
{
    const float* centers = (const float*)d_in[0];
    float* out = (float*)d_out;

    nn_min_kernel<<<NBLK_MIN, TPB>>>(centers);
    nn_combine_kernel<<<NBLK_CMB, CMB_TPB>>>();
    nn_final_kernel<<<1, NBLK_CMB>>>(out);
}

// round 7
// speedup vs baseline: 2.2705x; 1.3135x over previous
#include <cuda_runtime.h>
#include <math_constants.h>

// Problem constants (fixed: centers [8, 4096, 3] fp32)
#define BATCH    8
#define NPTS     4096
#define TPB      128              // threads per block (min kernel)
#define IPT      4                // i-points per thread
#define ITILE    (TPB * IPT)      // 512 i per block
#define NITILES  (NPTS / ITILE)   // 8
#define SSPLIT   16               // j-splits
#define JT       (NPTS / SSPLIT)  // 256 j per block
#define NBLK_MIN (BATCH * NITILES * SSPLIT)   // 1024
#define CMB_TPB  512
#define NBLK_CMB ((BATCH * NPTS) / CMB_TPB)   // 64
#define TARGET_F 0.2f

// Scratch (static device globals — no allocation allowed)
// per-point partial mins: [point][SSPLIT] floats = [point][4] float4  (2 MB)
__device__ float4 g_pmin4[BATCH * NPTS * SSPLIT / 4];
__device__ float  g_partials[NBLK_CMB];

// ---- packed f32x2 helpers (FFMA2: only reachable via PTX) ----
__device__ __forceinline__ unsigned long long pack2(float a, float b) {
    unsigned long long r;
    asm("mov.b64 %0, {%1, %2};" : "=l"(r) : "f"(a), "f"(b));
    return r;
}
__device__ __forceinline__ unsigned long long fma2(unsigned long long a,
                                                   unsigned long long b,
                                                   unsigned long long c) {
    unsigned long long d;
    asm("fma.rn.f32x2 %0, %1, %2, %3;" : "=l"(d) : "l"(a), "l"(b), "l"(c));
    return d;
}
__device__ __forceinline__ float2 unpack2(unsigned long long v) {
    float2 f;
    asm("mov.b64 {%0, %1}, %2;" : "=f"(f.x), "=f"(f.y) : "l"(v));
    return f;
}

__global__ void __launch_bounds__(TPB)
nn_min_kernel(const float* __restrict__ centers)
{
    // SoA j-tile: LDS.128 per array yields pre-packed {j,j+1} f32x2 lanes
    __shared__ __align__(16) float spx[JT], spy[JT], spz[JT], spw[JT];

    const int blk = blockIdx.x;
    const int s   = blk & (SSPLIT - 1);
    const int it  = (blk >> 4) & (NITILES - 1);
    const int b   = blk >> 7;
    const int tid = threadIdx.x;

    const float* cb = centers + (size_t)b * NPTS * 3;
    const int j_lo  = s  * JT;
    const int i_lo  = it * ITILE;

    for (int p = tid; p < JT; p += TPB) {
        float x = cb[3 * (j_lo + p) + 0];
        float y = cb[3 * (j_lo + p) + 1];
        float z = cb[3 * (j_lo + p) + 2];
        spx[p] = x; spy[p] = y; spz[p] = z;
        spw[p] = fmaf(x, x, fmaf(y, y, z * z));
    }

    // i-constants, pre-packed {c,c} once
    unsigned long long ax2[IPT], ay2[IPT], az2[IPT];
    float sqi[IPT], tmin[IPT];
    int   msel[IPT];   // local j index that equals this i (may be out of range)
    #pragma unroll
    for (int k = 0; k < IPT; ++k) {
        const int il = tid + k * TPB;
        const int gi = i_lo + il;
        float x = cb[3 * gi + 0];
        float y = cb[3 * gi + 1];
        float z = cb[3 * gi + 2];
        ax2[k] = pack2(-2.0f * x, -2.0f * x);
        ay2[k] = pack2(-2.0f * y, -2.0f * y);
        az2[k] = pack2(-2.0f * z, -2.0f * z);
        sqi[k] = fmaf(x, x, fmaf(y, y, z * z));
        tmin[k] = CUDART_INF_F;
        msel[k] = gi - j_lo;
    }
    __syncthreads();

    const ulonglong2* px2 = (const ulonglong2*)spx;
    const ulonglong2* py2 = (const ulonglong2*)spy;
    const ulonglong2* pz2 = (const ulonglong2*)spz;
    const ulonglong2* pw2 = (const ulonglong2*)spw;

    if ((s >> 1) != it) {
        // Off-diagonal block: clean loop, no compares
        #pragma unroll 2
        for (int q = 0; q < JT / 4; ++q) {
            const ulonglong2 px = px2[q], py = py2[q], pz = pz2[q], pw = pw2[q];
            #pragma unroll
            for (int k = 0; k < IPT; ++k) {
                unsigned long long t0 = fma2(pz.x, az2[k], pw.x);
                t0 = fma2(py.x, ay2[k], t0);
                t0 = fma2(px.x, ax2[k], t0);
                unsigned long long t1 = fma2(pz.y, az2[k], pw.y);
                t1 = fma2(py.y, ay2[k], t1);
                t1 = fma2(px.y, ax2[k], t1);
                float2 a = unpack2(t0), c = unpack2(t1);
                tmin[k] = fminf(tmin[k],
                                fminf(fminf(a.x, a.y), fminf(c.x, c.y)));
            }
        }
    } else {
        // Diagonal block (1/16 of blocks): predicate out j == i
        #pragma unroll 2
        for (int q = 0; q < JT / 4; ++q) {
            const int jb = q * 4;
            const ulonglong2 px = px2[q], py = py2[q], pz = pz2[q], pw = pw2[q];
            #pragma unroll
            for (int k = 0; k < IPT; ++k) {
                unsigned long long t0 = fma2(pz.x, az2[k], pw.x);
                t0 = fma2(py.x, ay2[k], t0);
                t0 = fma2(px.x, ax2[k], t0);
                unsigned long long t1 = fma2(pz.y, az2[k], pw.y);
                t1 = fma2(py.y, ay2[k], t1);
                t1 = fma2(px.y, ax2[k], t1);
                float2 a = unpack2(t0), c = unpack2(t1);
                const int m = msel[k];
                a.x = (jb + 0 == m) ? CUDART_INF_F : a.x;
                a.y = (jb + 1 == m) ? CUDART_INF_F : a.y;
                c.x = (jb + 2 == m) ? CUDART_INF_F : c.x;
                c.y = (jb + 3 == m) ? CUDART_INF_F : c.y;
                tmin[k] = fminf(tmin[k],
                                fminf(fminf(a.x, a.y), fminf(c.x, c.y)));
            }
        }
    }

    // Emit partial (sq_i + tmin) per i
    float* pm = (float*)g_pmin4;
    #pragma unroll
    for (int k = 0; k < IPT; ++k) {
        const int gi = b * NPTS + i_lo + tid + k * TPB;
        pm[(size_t)gi * SSPLIT + s] = sqi[k] + tmin[k];
    }
}

__global__ void __launch_bounds__(CMB_TPB)
nn_combine_kernel()
{
    __shared__ float red[CMB_TPB];
    const int tid = threadIdx.x;
    const int gi  = blockIdx.x * CMB_TPB + tid;

    float m = CUDART_INF_F;
    #pragma unroll
    for (int q = 0; q < SSPLIT / 4; ++q) {
        const float4 a = g_pmin4[gi * (SSPLIT / 4) + q];
        m = fminf(m, fminf(fminf(a.x, a.y), fminf(a.z, a.w)));
    }
    float d2   = fmaxf(m, 0.0f);          // clamp like reference
    float diff = sqrtf(d2) - TARGET_F;
    red[tid] = diff * diff;
    __syncthreads();
    #pragma unroll
    for (int st = CMB_TPB / 2; st > 0; st >>= 1) {
        if (tid < st) red[tid] += red[tid + st];
        __syncthreads();
    }
    if (tid == 0) g_partials[blockIdx.x] = red[0];
}

__global__ void __launch_bounds__(NBLK_CMB)
nn_final_kernel(float* __restrict__ out)
{
    __shared__ float red[NBLK_CMB];
    const int tid = threadIdx.x;
    red[tid] = g_partials[tid];
    __syncthreads();
    #pragma unroll
    for (int st = NBLK_CMB / 2; st > 0; st >>= 1) {
        if (tid < st) red[tid] += red[tid + st];
        __syncthreads();
    }
    if (tid == 0) out[0] = red[0] * (1.0f / (float)(BATCH * NPTS));
}

extern "C" void kernel_launch(void* const* d_in, const int* in_sizes, int n_in,
                              void* d_out, int out_size)
{
    const float* centers = (const float*)d_in[0];
    float* out = (float*)d_out;

    nn_min_kernel<<<NBLK_MIN, TPB>>>(centers);
    nn_combine_kernel<<<NBLK_CMB, CMB_TPB>>>();
    nn_final_kernel<<<1, NBLK_CMB>>>(out);
}